// round 15
// baseline (speedup 1.0000x reference)
#include <cuda_runtime.h>
#include <cuda_fp16.h>
#include <mma.h>
#include <cstdint>

using namespace nvcuda;

#define NN   50000
#define PADN 50176
#define PADDEG 53248
#define NBLK 208                 // PADDEG / 256
#define EE   800000
#define HH   128
#define GG   64
#define OUTD 10
#define C0END 25088              // 196 * 128, node-chunk boundary

// ---------------- scratch (device globals; no dynamic allocation) ----------
__device__ __half g_h16a[(size_t)PADN * HH];
__device__ __half g_h16b[(size_t)PADN * HH];
__device__ __half g_w16[3 * HH * HH];
__device__ int    g_batch[NN];
__device__ int    g_deg[PADDEG];
__device__ int    g_rowstart[NN + 1];
__device__ int    g_cursor[NN];
__device__ float  g_dinv[NN];
__device__ int    g_csri[EE];
__device__ int    g_bsum[NBLK];
__device__ float  g_pooled[GG * HH];
__device__ float  g_cnts[GG];
__device__ int    g_is64;

__device__ __forceinline__ int clampN(int v) { return min(max(v, 0), NN - 1); }

__device__ __forceinline__ void decode_edge(const void* p, int e, int& s, int& d) {
    if (g_is64) {
        const long long* q = (const long long*)p;
        s = (int)q[e];
        d = (int)q[EE + e];
    } else {
        const int* q = (const int*)p;
        s = q[e];
        d = q[EE + e];
    }
    s = clampN(s);
    d = clampN(d);
}

// ---------------- init: zero scratch + dtype detect --------------------------
__global__ void k_init(const int* __restrict__ p) {
    if (blockIdx.x < NBLK) {
        int i = blockIdx.x * 256 + threadIdx.x;
        g_deg[i] = 0;
        if (i < GG * HH) g_pooled[i] = 0.0f;
        if (i < GG) g_cnts[i] = 0.0f;
    } else {
        __shared__ int any;
        if (threadIdx.x == 0) any = 0;
        __syncthreads();
        int v = 0;
        for (int i = threadIdx.x; i < 4096; i += blockDim.x) v |= p[2 * i + 1];
        if (v) atomicOr(&any, 1);
        __syncthreads();
        if (threadIdx.x == 0) g_is64 = any ? 0 : 1;
    }
}

__global__ void k_cvtw(const float* __restrict__ W0,
                       const float* __restrict__ W1,
                       const float* __restrict__ W2) {
    const int WQ = HH * HH / 4;
    int i = blockIdx.x * blockDim.x + threadIdx.x;
    if (i >= 3 * WQ) return;
    const float4* src;
    int off;
    if (i < WQ)          { src = (const float4*)W0; off = i; }
    else if (i < 2 * WQ) { src = (const float4*)W1; off = i - WQ; }
    else                 { src = (const float4*)W2; off = i - 2 * WQ; }
    float4 v = src[off];
    __half2 a = __floats2half2_rn(v.x, v.y);
    __half2 b = __floats2half2_rn(v.z, v.w);
    uint2 o;
    o.x = *(unsigned int*)&a;
    o.y = *(unsigned int*)&b;
    ((uint2*)g_w16)[i] = o;
}

__global__ void k_hist(const void* __restrict__ p) {
    int e = blockIdx.x * blockDim.x + threadIdx.x;
    if (e >= EE) return;
    int s, d;
    decode_edge(p, e, s, d);
    atomicAdd(&g_deg[d], 1);
}

__global__ void k_cvt_batch(const void* __restrict__ p) {
    int n = blockIdx.x * blockDim.x + threadIdx.x;
    if (n >= NN) return;
    int b;
    if (g_is64) b = (int)((const long long*)p)[n];
    else        b = ((const int*)p)[n];
    b = min(max(b, 0), GG - 1);
    g_batch[n] = b;
    unsigned am = __activemask();
    unsigned mask = __match_any_sync(am, b);
    int leader = __ffs(mask) - 1;
    if ((threadIdx.x & 31) == leader)
        atomicAdd(&g_cnts[b], (float)__popc(mask));
}

// ---------------- parallel scan ----------------------------------------------
__global__ void __launch_bounds__(256) k_scan1() {
    __shared__ int sh[256];
    int t = threadIdx.x;
    int i = blockIdx.x * 256 + t;
    sh[t] = g_deg[i];
    __syncthreads();
#pragma unroll
    for (int off = 128; off > 0; off >>= 1) {
        if (t < off) sh[t] += sh[t + off];
        __syncthreads();
    }
    if (t == 0) g_bsum[blockIdx.x] = sh[0];
}

__global__ void __launch_bounds__(256) k_scan3() {
    __shared__ int bs[256];
    __shared__ int ws[8];
    __shared__ int boff_s;
    int t = threadIdx.x;
    bs[t] = (t < NBLK) ? g_bsum[t] : 0;
    __syncthreads();
#pragma unroll
    for (int off = 1; off < 256; off <<= 1) {
        int u = (t >= off) ? bs[t - off] : 0;
        __syncthreads();
        bs[t] += u;
        __syncthreads();
    }
    if (t == 0) boff_s = (blockIdx.x == 0) ? 0 : bs[blockIdx.x - 1];
    __syncthreads();

    int i = blockIdx.x * 256 + t;
    int lane = t & 31, w = t >> 5;
    int v = g_deg[i];
    int inc = v;
#pragma unroll
    for (int off = 1; off < 32; off <<= 1) {
        int u = __shfl_up_sync(0xffffffffu, inc, off);
        if (lane >= off) inc += u;
    }
    if (lane == 31) ws[w] = inc;
    __syncthreads();
    if (t == 0) {
        int run = 0;
#pragma unroll
        for (int k = 0; k < 8; k++) { int tmp = ws[k]; ws[k] = run; run += tmp; }
    }
    __syncthreads();
    int excl = inc - v + ws[w] + boff_s;
    if (i <= NN) g_rowstart[i] = excl;
    if (i < NN) {
        g_cursor[i] = excl;
        g_dinv[i] = rsqrtf((float)v + 1.0f);
    }
}

__global__ void k_fill(const void* __restrict__ p) {
    int e = blockIdx.x * blockDim.x + threadIdx.x;
    if (e >= EE) return;
    int s, d;
    decode_edge(p, e, s, d);
    int pos = atomicAdd(&g_cursor[d], 1);
    g_csri[pos] = s;
}

// ---------------- tensor-core GEMM -------------------------------------------
#define LDA 136
#define SMEM_GEMM (2 * 128 * LDA * (int)sizeof(__half))   // 69,632 B

template <typename LOADA>
__device__ __forceinline__ void gemm_body(LOADA loadA,
                                          const __half* __restrict__ W,
                                          __half* __restrict__ C,
                                          int nRows) {
    extern __shared__ __half sm[];
    __half* As = sm;
    __half* Ws = sm + 128 * LDA;

    int tid  = threadIdx.x;
    int w    = tid >> 5;
    int row0 = blockIdx.x * 128;

    loadA(As, row0, tid, nRows);
#pragma unroll
    for (int i = 0; i < 8; i++) {
        int idx = tid + i * 256;
        int r  = idx >> 4;
        int c8 = idx & 15;
        uint4 v = *(const uint4*)(W + r * 128 + c8 * 8);
        *(uint4*)(Ws + r * LDA + c8 * 8) = v;
    }
    __syncthreads();

    int wr = w >> 1, wc = w & 1;
    int r0w = wr * 32, c0w = wc * 64;

    wmma::fragment<wmma::accumulator, 16, 16, 16, float> c[2][4];
#pragma unroll
    for (int i = 0; i < 2; i++)
#pragma unroll
        for (int j = 0; j < 4; j++) wmma::fill_fragment(c[i][j], 0.0f);

#pragma unroll
    for (int k0 = 0; k0 < 128; k0 += 16) {
        wmma::fragment<wmma::matrix_a, 16, 16, 16, __half, wmma::row_major> a[2];
        wmma::fragment<wmma::matrix_b, 16, 16, 16, __half, wmma::row_major> b[4];
#pragma unroll
        for (int i = 0; i < 2; i++)
            wmma::load_matrix_sync(a[i], As + (r0w + i * 16) * LDA + k0, LDA);
#pragma unroll
        for (int j = 0; j < 4; j++)
            wmma::load_matrix_sync(b[j], Ws + k0 * LDA + c0w + j * 16, LDA);
#pragma unroll
        for (int i = 0; i < 2; i++)
#pragma unroll
            for (int j = 0; j < 4; j++)
                wmma::mma_sync(c[i][j], a[i], b[j], c[i][j]);
    }

#pragma unroll
    for (int i = 0; i < 2; i++) {
#pragma unroll
        for (int j = 0; j < 4; j++) {
            wmma::fragment<wmma::accumulator, 16, 16, 16, __half> hc;
#pragma unroll
            for (int e = 0; e < hc.num_elements; e++)
                hc.x[e] = __float2half(c[i][j].x[e]);
            wmma::store_matrix_sync(C + (size_t)(row0 + r0w + i * 16) * 128 + c0w + j * 16,
                                    hc, 128, wmma::mem_row_major);
        }
    }
}

__global__ void __launch_bounds__(256) k_gemm(const __half* __restrict__ A,
                                              const __half* __restrict__ W,
                                              __half* __restrict__ C,
                                              int nRows) {
    gemm_body([A](__half* As, int row0, int tid, int nR) {
#pragma unroll
        for (int i = 0; i < 8; i++) {
            int idx = tid + i * 256;
            int r  = idx >> 4;
            int c8 = idx & 15;
            uint4 v = make_uint4(0u, 0u, 0u, 0u);
            if (row0 + r < nR)
                v = *(const uint4*)(A + (size_t)(row0 + r) * 128 + c8 * 8);
            *(uint4*)(As + r * LDA + c8 * 8) = v;
        }
    }, W, C, nRows);
}

__global__ void __launch_bounds__(256) k_gemm_f32in(const float* __restrict__ A,
                                                    const __half* __restrict__ W,
                                                    __half* __restrict__ C,
                                                    int nRows) {
    gemm_body([A](__half* As, int row0, int tid, int nR) {
#pragma unroll
        for (int i = 0; i < 16; i++) {
            int idx = tid + i * 256;
            int r  = idx >> 5;
            int c4 = idx & 31;
            float4 v = make_float4(0.f, 0.f, 0.f, 0.f);
            if (row0 + r < nR)
                v = *(const float4*)(A + (size_t)(row0 + r) * 128 + c4 * 4);
            __half2 a = __floats2half2_rn(v.x, v.y);
            __half2 b = __floats2half2_rn(v.z, v.w);
            uint2 o;
            o.x = *(unsigned int*)&a;
            o.y = *(unsigned int*)&b;
            *(uint2*)(As + r * LDA + c4 * 4) = o;
        }
    }, W, C, nRows);
}

// ---------------- gather helpers --------------------------------------------
__device__ __forceinline__ void unp8(uint4 v, float* f) {
    float2 a = __half22float2(*(__half2*)&v.x);
    float2 b = __half22float2(*(__half2*)&v.y);
    float2 c = __half22float2(*(__half2*)&v.z);
    float2 d = __half22float2(*(__half2*)&v.w);
    f[0] = a.x; f[1] = a.y; f[2] = b.x; f[3] = b.y;
    f[4] = c.x; f[5] = c.y; f[6] = d.x; f[7] = d.y;
}

__device__ __forceinline__ uint4 pack8(const float* acc) {
    __half2 p0 = __floats2half2_rn(acc[0], acc[1]);
    __half2 p1 = __floats2half2_rn(acc[2], acc[3]);
    __half2 p2 = __floats2half2_rn(acc[4], acc[5]);
    __half2 p3 = __floats2half2_rn(acc[6], acc[7]);
    uint4 o;
    o.x = *(unsigned int*)&p0;
    o.y = *(unsigned int*)&p1;
    o.z = *(unsigned int*)&p2;
    o.w = *(unsigned int*)&p3;
    return o;
}

// ---------------- gather, weighted (layer 1; chunked by node range) ---------
// writes a1ps[n] = dinv[n] * relu( dinv[n] * (sum_s dinv[s]h[s] + dinv[n]h[n]) )
__global__ void __launch_bounds__(256) k_gather_w(const __half* __restrict__ h,
                                                  __half* __restrict__ out,
                                                  int nodeBase, int nodeEnd) {
    int hw   = nodeBase + ((blockIdx.x * blockDim.x + threadIdx.x) >> 4);
    int lane = threadIdx.x & 15;
    if (hw >= nodeEnd) return;
    int n = hw;

    const uint4* h4 = (const uint4*)h;
    float di = g_dinv[n];
    float acc[8], f0[8], f1[8], f2[8], f3[8];
    unp8(h4[(size_t)n * 16 + lane], acc);
#pragma unroll
    for (int k = 0; k < 8; k++) acc[k] *= di;

    int i   = g_rowstart[n];
    int end = g_rowstart[n + 1];
    for (; i + 3 < end; i += 4) {
        int s0 = g_csri[i],     s1 = g_csri[i + 1];
        int s2 = g_csri[i + 2], s3 = g_csri[i + 3];
        float w0 = __ldg(&g_dinv[s0]), w1 = __ldg(&g_dinv[s1]);
        float w2 = __ldg(&g_dinv[s2]), w3 = __ldg(&g_dinv[s3]);
        uint4 v0 = h4[(size_t)s0 * 16 + lane];
        uint4 v1 = h4[(size_t)s1 * 16 + lane];
        uint4 v2 = h4[(size_t)s2 * 16 + lane];
        uint4 v3 = h4[(size_t)s3 * 16 + lane];
        unp8(v0, f0); unp8(v1, f1); unp8(v2, f2); unp8(v3, f3);
#pragma unroll
        for (int k = 0; k < 8; k++)
            acc[k] += w0 * f0[k] + w1 * f1[k] + w2 * f2[k] + w3 * f3[k];
    }
    for (; i < end; i++) {
        int s0 = g_csri[i];
        float w0 = __ldg(&g_dinv[s0]);
        uint4 v0 = h4[(size_t)s0 * 16 + lane];
        unp8(v0, f0);
#pragma unroll
        for (int k = 0; k < 8; k++) acc[k] += w0 * f0[k];
    }
#pragma unroll
    for (int k = 0; k < 8; k++) {
        acc[k] *= di;
        acc[k] = fmaxf(acc[k], 0.0f);
        acc[k] *= di;
    }
    ((uint4*)out)[(size_t)n * 16 + lane] = pack8(acc);
}

// ---------------- gather, add-only (layers 2,3; chunked) --------------------
__global__ void __launch_bounds__(256) k_gather_f(const __half* __restrict__ h,
                                                  __half* __restrict__ out,
                                                  int mid, int nodeBase, int nodeEnd) {
    int hw   = nodeBase + ((blockIdx.x * blockDim.x + threadIdx.x) >> 4);
    int lane = threadIdx.x & 15;
    if (hw >= nodeEnd) return;
    int n = hw;

    const uint4* h4 = (const uint4*)h;
    float acc[8], f0[8], f1[8], f2[8], f3[8];
    unp8(h4[(size_t)n * 16 + lane], acc);

    int i   = g_rowstart[n];
    int end = g_rowstart[n + 1];
    for (; i + 7 < end; i += 8) {
        int   si[8];
        uint4 vi[8];
#pragma unroll
        for (int j = 0; j < 8; j++) si[j] = g_csri[i + j];
#pragma unroll
        for (int j = 0; j < 8; j++) vi[j] = h4[(size_t)si[j] * 16 + lane];
#pragma unroll
        for (int j = 0; j < 8; j++) {
            unp8(vi[j], f0);
#pragma unroll
            for (int k = 0; k < 8; k++) acc[k] += f0[k];
        }
    }
    for (; i + 3 < end; i += 4) {
        int s0 = g_csri[i],     s1 = g_csri[i + 1];
        int s2 = g_csri[i + 2], s3 = g_csri[i + 3];
        uint4 v0 = h4[(size_t)s0 * 16 + lane];
        uint4 v1 = h4[(size_t)s1 * 16 + lane];
        uint4 v2 = h4[(size_t)s2 * 16 + lane];
        uint4 v3 = h4[(size_t)s3 * 16 + lane];
        unp8(v0, f0); unp8(v1, f1); unp8(v2, f2); unp8(v3, f3);
#pragma unroll
        for (int k = 0; k < 8; k++)
            acc[k] += f0[k] + f1[k] + f2[k] + f3[k];
    }
    for (; i < end; i++) {
        int s0 = g_csri[i];
        uint4 v0 = h4[(size_t)s0 * 16 + lane];
        unp8(v0, f0);
#pragma unroll
        for (int k = 0; k < 8; k++) acc[k] += f0[k];
    }

    float di = g_dinv[n];
    if (mid) {
#pragma unroll
        for (int k = 0; k < 8; k++) {
            acc[k] *= di;
            acc[k] = fmaxf(acc[k], 0.0f);
            acc[k] *= di;
        }
    } else {
#pragma unroll
        for (int k = 0; k < 8; k++) acc[k] *= di;
    }
    ((uint4*)out)[(size_t)n * 16 + lane] = pack8(acc);
}

// ---------------- pooling ----------------------------------------------------
__global__ void __launch_bounds__(128) k_pool(const __half* __restrict__ h) {
    int warp = threadIdx.x >> 5;
    int lane = threadIdx.x & 31;
    int n0 = blockIdx.x * 256 + warp * 64;
    if (n0 >= NN) return;
    int n1 = n0 + 64; if (n1 > NN) n1 = NN;

    const uint2* h2 = (const uint2*)h;
    float a0 = 0.f, a1 = 0.f, a2 = 0.f, a3 = 0.f;
    int g = g_batch[n0];
    for (int n = n0; n < n1; n++) {
        int b = g_batch[n];
        if (b != g) {
            int base = g * HH + lane * 4;
            atomicAdd(&g_pooled[base + 0], a0);
            atomicAdd(&g_pooled[base + 1], a1);
            atomicAdd(&g_pooled[base + 2], a2);
            atomicAdd(&g_pooled[base + 3], a3);
            a0 = a1 = a2 = a3 = 0.f;
            g = b;
        }
        uint2 v = h2[(size_t)n * 32 + lane];
        float2 x = __half22float2(*(__half2*)&v.x);
        float2 y = __half22float2(*(__half2*)&v.y);
        a0 += x.x; a1 += x.y; a2 += y.x; a3 += y.y;
    }
    int base = g * HH + lane * 4;
    atomicAdd(&g_pooled[base + 0], a0);
    atomicAdd(&g_pooled[base + 1], a1);
    atomicAdd(&g_pooled[base + 2], a2);
    atomicAdd(&g_pooled[base + 3], a3);
}

// ---------------- final MLP --------------------------------------------------
__global__ void __launch_bounds__(128) k_mlp(const float* __restrict__ M0w,
                                             const float* __restrict__ M0b,
                                             const float* __restrict__ M1w,
                                             const float* __restrict__ M1b,
                                             float* __restrict__ out) {
    __shared__ float pv[HH];
    __shared__ float hid[HH];
    int g = blockIdx.x;
    int t = threadIdx.x;
    pv[t] = g_pooled[g * HH + t] / fmaxf(g_cnts[g], 1.0f);
    __syncthreads();
    float s = M0b[t];
#pragma unroll 8
    for (int k = 0; k < HH; k++) s += pv[k] * M0w[k * HH + t];
    hid[t] = fmaxf(s, 0.0f);
    __syncthreads();
    if (t < OUTD) {
        float s2 = M1b[t];
#pragma unroll 8
        for (int j = 0; j < HH; j++) s2 += hid[j] * M1w[j * OUTD + t];
        out[g * OUTD + t] = s2;
    }
}

// ---------------- launch ----------------------------------------------------
extern "C" void kernel_launch(void* const* d_in, const int* in_sizes, int n_in,
                              void* d_out, int out_size) {
    const float* x   = (const float*)d_in[0];
    const float* W0  = (const float*)d_in[1];
    const float* W1  = (const float*)d_in[2];
    const float* W2  = (const float*)d_in[3];
    const float* M0w = (const float*)d_in[4];
    const float* M0b = (const float*)d_in[5];
    const float* M1w = (const float*)d_in[6];
    const float* M1b = (const float*)d_in[7];
    const void*  ei  = d_in[8];
    const void*  bat = d_in[9];
    float* out = (float*)d_out;

    __half* hA = nullptr;
    __half* hB = nullptr;
    __half* w16 = nullptr;
    cudaGetSymbolAddress((void**)&hA, g_h16a);
    cudaGetSymbolAddress((void**)&hB, g_h16b);
    cudaGetSymbolAddress((void**)&w16, g_w16);

    static int init_done = 0;
    static cudaStream_t s2 = nullptr;
    static cudaEvent_t evs[8];
    static int streams_ok = 0;
    if (!init_done) {
        cudaFuncSetAttribute(k_gemm, cudaFuncAttributeMaxDynamicSharedMemorySize, SMEM_GEMM);
        cudaFuncSetAttribute(k_gemm_f32in, cudaFuncAttributeMaxDynamicSharedMemorySize, SMEM_GEMM);
        bool ok = cudaStreamCreateWithFlags(&s2, cudaStreamNonBlocking) == cudaSuccess;
        for (int i = 0; i < 8 && ok; i++)
            ok = cudaEventCreateWithFlags(&evs[i], cudaEventDisableTiming) == cudaSuccess;
        streams_ok = ok ? 1 : 0;
        init_done = 1;
    }

    const int T = 256;
    int gN = (NN + T - 1) / T;              // 196
    int gE = (EE + T - 1) / T;              // 3125
    int gGemm   = (NN + 127) / 128;         // 391
    int gGather = (NN * 16 + T - 1) / T;    // 3125
    int gW      = (3 * HH * HH / 4 + T - 1) / T;   // 48
    // chunk sizes (node ranges [0,C0END) and [C0END,NN))
    const int c1n = NN - C0END;                       // 24912
    int gGa0 = (C0END * 16 + T - 1) / T;              // 1568
    int gGa1 = (c1n * 16 + T - 1) / T;                // 1557
    int gGe0 = C0END / 128;                           // 196
    int gGe1 = (c1n + 127) / 128;                     // 195

    cudaStream_t sb = streams_ok ? s2 : (cudaStream_t)0;

    // init, then fork chains A (CSR) / B (weights + gemm1 + batch)
    k_init<<<NBLK + 1, 256>>>((const int*)ei);
    if (streams_ok) { cudaEventRecord(evs[0], 0); cudaStreamWaitEvent(s2, evs[0], 0); }
    k_hist<<<gE, T>>>(ei);
    k_scan1<<<NBLK, 256>>>();
    k_scan3<<<NBLK, 256>>>();
    k_fill<<<gE, T>>>(ei);
    k_cvtw<<<gW, T, 0, sb>>>(W0, W1, W2);
    k_gemm_f32in<<<gGemm, T, SMEM_GEMM, sb>>>(x, w16, hB, NN);
    k_cvt_batch<<<gN, T, 0, sb>>>(bat);
    if (streams_ok) { cudaEventRecord(evs[1], s2); cudaStreamWaitEvent(0, evs[1], 0); }

    if (streams_ok) {
        // ---- layer 1 gather chunked, layer-2 gemm pipelined on s2 ----
        k_gather_w<<<gGa0, T>>>(hB, hA, 0, C0END);
        cudaEventRecord(evs[2], 0);
        k_gather_w<<<gGa1, T>>>(hB, hA, C0END, NN);
        cudaEventRecord(evs[3], 0);
        cudaStreamWaitEvent(s2, evs[2], 0);
        k_gemm<<<gGe0, T, SMEM_GEMM, s2>>>(hA, w16 + HH * HH, hB, C0END);
        cudaStreamWaitEvent(s2, evs[3], 0);
        k_gemm<<<gGe1, T, SMEM_GEMM, s2>>>(hA + (size_t)C0END * HH, w16 + HH * HH,
                                           hB + (size_t)C0END * HH, c1n);
        cudaEventRecord(evs[4], s2);
        cudaStreamWaitEvent(0, evs[4], 0);

        // ---- layer 2 gather chunked, layer-3 gemm pipelined on s2 ----
        k_gather_f<<<gGa0, T>>>(hB, hA, 1, 0, C0END);
        cudaEventRecord(evs[5], 0);
        k_gather_f<<<gGa1, T>>>(hB, hA, 1, C0END, NN);
        cudaEventRecord(evs[6], 0);
        cudaStreamWaitEvent(s2, evs[5], 0);
        k_gemm<<<gGe0, T, SMEM_GEMM, s2>>>(hA, w16 + 2 * HH * HH, hB, C0END);
        cudaStreamWaitEvent(s2, evs[6], 0);
        k_gemm<<<gGe1, T, SMEM_GEMM, s2>>>(hA + (size_t)C0END * HH, w16 + 2 * HH * HH,
                                           hB + (size_t)C0END * HH, c1n);
        cudaEventRecord(evs[7], s2);
        cudaStreamWaitEvent(0, evs[7], 0);
    } else {
        // serialized fallback
        k_gather_w<<<gGather, T>>>(hB, hA, 0, NN);
        k_gemm<<<gGemm, T, SMEM_GEMM>>>(hA, w16 + HH * HH, hB, NN);
        k_gather_f<<<gGather, T>>>(hB, hA, 1, 0, NN);
        k_gemm<<<gGemm, T, SMEM_GEMM>>>(hA, w16 + 2 * HH * HH, hB, NN);
    }

    // final aggregation (no relu) + pool + MLP
    k_gather_f<<<gGather, T>>>(hB, hA, 0, 0, NN);
    k_pool<<<(NN + 255) / 256, 128>>>(hA);
    k_mlp<<<GG, 128>>>(M0w, M0b, M1w, M1b, out);
}

// round 16
// speedup vs baseline: 1.1906x; 1.1906x over previous
#include <cuda_runtime.h>
#include <cuda_fp16.h>
#include <mma.h>
#include <cstdint>

using namespace nvcuda;

#define NN   50000
#define PADN 50176
#define PADDEG 53248
#define NBLK 208                 // PADDEG / 256
#define EE   800000
#define HH   128
#define GG   64
#define OUTD 10

// ---------------- scratch (device globals; no dynamic allocation) ----------
__device__ __half g_h16a[(size_t)PADN * HH];
__device__ __half g_h16b[(size_t)PADN * HH];
__device__ __half g_w16[3 * HH * HH];
__device__ int    g_batch[NN];
__device__ int    g_deg[PADDEG];
__device__ int    g_rowstart[NN + 1];
__device__ int    g_cursor[NN];
__device__ float  g_dinv[NN];
__device__ int    g_csri[EE];
__device__ int    g_bsum[NBLK];
__device__ float  g_pooled[GG * HH];
__device__ float  g_cnts[GG];
__device__ int    g_is64;

__device__ __forceinline__ int clampN(int v) { return min(max(v, 0), NN - 1); }

__device__ __forceinline__ void decode_edge(const void* p, int e, int& s, int& d) {
    if (g_is64) {
        const long long* q = (const long long*)p;
        s = (int)q[e];
        d = (int)q[EE + e];
    } else {
        const int* q = (const int*)p;
        s = q[e];
        d = q[EE + e];
    }
    s = clampN(s);
    d = clampN(d);
}

// ---------------- init: zero scratch + dtype detect --------------------------
__global__ void k_init(const int* __restrict__ p) {
    if (blockIdx.x < NBLK) {
        int i = blockIdx.x * 256 + threadIdx.x;
        g_deg[i] = 0;
        if (i < GG * HH) g_pooled[i] = 0.0f;
        if (i < GG) g_cnts[i] = 0.0f;
    } else {
        __shared__ int any;
        if (threadIdx.x == 0) any = 0;
        __syncthreads();
        int v = 0;
        for (int i = threadIdx.x; i < 4096; i += blockDim.x) v |= p[2 * i + 1];
        if (v) atomicOr(&any, 1);
        __syncthreads();
        if (threadIdx.x == 0) g_is64 = any ? 0 : 1;
    }
}

__global__ void k_cvtw(const float* __restrict__ W0,
                       const float* __restrict__ W1,
                       const float* __restrict__ W2) {
    const int WQ = HH * HH / 4;
    int i = blockIdx.x * blockDim.x + threadIdx.x;
    if (i >= 3 * WQ) return;
    const float4* src;
    int off;
    if (i < WQ)          { src = (const float4*)W0; off = i; }
    else if (i < 2 * WQ) { src = (const float4*)W1; off = i - WQ; }
    else                 { src = (const float4*)W2; off = i - 2 * WQ; }
    float4 v = src[off];
    __half2 a = __floats2half2_rn(v.x, v.y);
    __half2 b = __floats2half2_rn(v.z, v.w);
    uint2 o;
    o.x = *(unsigned int*)&a;
    o.y = *(unsigned int*)&b;
    ((uint2*)g_w16)[i] = o;
}

__global__ void k_hist(const void* __restrict__ p) {
    int e = blockIdx.x * blockDim.x + threadIdx.x;
    if (e >= EE) return;
    int s, d;
    decode_edge(p, e, s, d);
    atomicAdd(&g_deg[d], 1);
}

__global__ void k_cvt_batch(const void* __restrict__ p) {
    int n = blockIdx.x * blockDim.x + threadIdx.x;
    if (n >= NN) return;
    int b;
    if (g_is64) b = (int)((const long long*)p)[n];
    else        b = ((const int*)p)[n];
    b = min(max(b, 0), GG - 1);
    g_batch[n] = b;
    unsigned am = __activemask();
    unsigned mask = __match_any_sync(am, b);
    int leader = __ffs(mask) - 1;
    if ((threadIdx.x & 31) == leader)
        atomicAdd(&g_cnts[b], (float)__popc(mask));
}

// ---------------- parallel scan ----------------------------------------------
__global__ void __launch_bounds__(256) k_scan1() {
    __shared__ int sh[256];
    int t = threadIdx.x;
    int i = blockIdx.x * 256 + t;
    sh[t] = g_deg[i];
    __syncthreads();
#pragma unroll
    for (int off = 128; off > 0; off >>= 1) {
        if (t < off) sh[t] += sh[t + off];
        __syncthreads();
    }
    if (t == 0) g_bsum[blockIdx.x] = sh[0];
}

__global__ void __launch_bounds__(256) k_scan3() {
    __shared__ int bs[256];
    __shared__ int ws[8];
    __shared__ int boff_s;
    int t = threadIdx.x;
    bs[t] = (t < NBLK) ? g_bsum[t] : 0;
    __syncthreads();
#pragma unroll
    for (int off = 1; off < 256; off <<= 1) {
        int u = (t >= off) ? bs[t - off] : 0;
        __syncthreads();
        bs[t] += u;
        __syncthreads();
    }
    if (t == 0) boff_s = (blockIdx.x == 0) ? 0 : bs[blockIdx.x - 1];
    __syncthreads();

    int i = blockIdx.x * 256 + t;
    int lane = t & 31, w = t >> 5;
    int v = g_deg[i];
    int inc = v;
#pragma unroll
    for (int off = 1; off < 32; off <<= 1) {
        int u = __shfl_up_sync(0xffffffffu, inc, off);
        if (lane >= off) inc += u;
    }
    if (lane == 31) ws[w] = inc;
    __syncthreads();
    if (t == 0) {
        int run = 0;
#pragma unroll
        for (int k = 0; k < 8; k++) { int tmp = ws[k]; ws[k] = run; run += tmp; }
    }
    __syncthreads();
    int excl = inc - v + ws[w] + boff_s;
    if (i <= NN) g_rowstart[i] = excl;
    if (i < NN) {
        g_cursor[i] = excl;
        g_dinv[i] = rsqrtf((float)v + 1.0f);
    }
}

__global__ void k_fill(const void* __restrict__ p) {
    int e = blockIdx.x * blockDim.x + threadIdx.x;
    if (e >= EE) return;
    int s, d;
    decode_edge(p, e, s, d);
    int pos = atomicAdd(&g_cursor[d], 1);
    g_csri[pos] = s;
}

// ---------------- tensor-core GEMM -------------------------------------------
#define LDA 136
#define SMEM_GEMM (2 * 128 * LDA * (int)sizeof(__half))   // 69,632 B

template <typename LOADA>
__device__ __forceinline__ void gemm_body(LOADA loadA,
                                          const __half* __restrict__ W,
                                          __half* __restrict__ C,
                                          int nRows) {
    extern __shared__ __half sm[];
    __half* As = sm;
    __half* Ws = sm + 128 * LDA;

    int tid  = threadIdx.x;
    int w    = tid >> 5;
    int row0 = blockIdx.x * 128;

    loadA(As, row0, tid, nRows);
#pragma unroll
    for (int i = 0; i < 8; i++) {
        int idx = tid + i * 256;
        int r  = idx >> 4;
        int c8 = idx & 15;
        uint4 v = *(const uint4*)(W + r * 128 + c8 * 8);
        *(uint4*)(Ws + r * LDA + c8 * 8) = v;
    }
    __syncthreads();

    int wr = w >> 1, wc = w & 1;
    int r0w = wr * 32, c0w = wc * 64;

    wmma::fragment<wmma::accumulator, 16, 16, 16, float> c[2][4];
#pragma unroll
    for (int i = 0; i < 2; i++)
#pragma unroll
        for (int j = 0; j < 4; j++) wmma::fill_fragment(c[i][j], 0.0f);

#pragma unroll
    for (int k0 = 0; k0 < 128; k0 += 16) {
        wmma::fragment<wmma::matrix_a, 16, 16, 16, __half, wmma::row_major> a[2];
        wmma::fragment<wmma::matrix_b, 16, 16, 16, __half, wmma::row_major> b[4];
#pragma unroll
        for (int i = 0; i < 2; i++)
            wmma::load_matrix_sync(a[i], As + (r0w + i * 16) * LDA + k0, LDA);
#pragma unroll
        for (int j = 0; j < 4; j++)
            wmma::load_matrix_sync(b[j], Ws + k0 * LDA + c0w + j * 16, LDA);
#pragma unroll
        for (int i = 0; i < 2; i++)
#pragma unroll
            for (int j = 0; j < 4; j++)
                wmma::mma_sync(c[i][j], a[i], b[j], c[i][j]);
    }

#pragma unroll
    for (int i = 0; i < 2; i++) {
#pragma unroll
        for (int j = 0; j < 4; j++) {
            wmma::fragment<wmma::accumulator, 16, 16, 16, __half> hc;
#pragma unroll
            for (int e = 0; e < hc.num_elements; e++)
                hc.x[e] = __float2half(c[i][j].x[e]);
            wmma::store_matrix_sync(C + (size_t)(row0 + r0w + i * 16) * 128 + c0w + j * 16,
                                    hc, 128, wmma::mem_row_major);
        }
    }
}

__global__ void __launch_bounds__(256) k_gemm(const __half* __restrict__ A,
                                              const __half* __restrict__ W,
                                              __half* __restrict__ C,
                                              int nRows) {
    gemm_body([A](__half* As, int row0, int tid, int nR) {
#pragma unroll
        for (int i = 0; i < 8; i++) {
            int idx = tid + i * 256;
            int r  = idx >> 4;
            int c8 = idx & 15;
            uint4 v = make_uint4(0u, 0u, 0u, 0u);
            if (row0 + r < nR)
                v = *(const uint4*)(A + (size_t)(row0 + r) * 128 + c8 * 8);
            *(uint4*)(As + r * LDA + c8 * 8) = v;
        }
    }, W, C, nRows);
}

__global__ void __launch_bounds__(256) k_gemm_f32in(const float* __restrict__ A,
                                                    const __half* __restrict__ W,
                                                    __half* __restrict__ C,
                                                    int nRows) {
    gemm_body([A](__half* As, int row0, int tid, int nR) {
#pragma unroll
        for (int i = 0; i < 16; i++) {
            int idx = tid + i * 256;
            int r  = idx >> 5;
            int c4 = idx & 31;
            float4 v = make_float4(0.f, 0.f, 0.f, 0.f);
            if (row0 + r < nR)
                v = *(const float4*)(A + (size_t)(row0 + r) * 128 + c4 * 4);
            __half2 a = __floats2half2_rn(v.x, v.y);
            __half2 b = __floats2half2_rn(v.z, v.w);
            uint2 o;
            o.x = *(unsigned int*)&a;
            o.y = *(unsigned int*)&b;
            *(uint2*)(As + r * LDA + c4 * 4) = o;
        }
    }, W, C, nRows);
}

// ---------------- gather helpers --------------------------------------------
__device__ __forceinline__ void unp8(uint4 v, float* f) {
    float2 a = __half22float2(*(__half2*)&v.x);
    float2 b = __half22float2(*(__half2*)&v.y);
    float2 c = __half22float2(*(__half2*)&v.z);
    float2 d = __half22float2(*(__half2*)&v.w);
    f[0] = a.x; f[1] = a.y; f[2] = b.x; f[3] = b.y;
    f[4] = c.x; f[5] = c.y; f[6] = d.x; f[7] = d.y;
}

__device__ __forceinline__ uint4 pack8(const float* acc) {
    __half2 p0 = __floats2half2_rn(acc[0], acc[1]);
    __half2 p1 = __floats2half2_rn(acc[2], acc[3]);
    __half2 p2 = __floats2half2_rn(acc[4], acc[5]);
    __half2 p3 = __floats2half2_rn(acc[6], acc[7]);
    uint4 o;
    o.x = *(unsigned int*)&p0;
    o.y = *(unsigned int*)&p1;
    o.z = *(unsigned int*)&p2;
    o.w = *(unsigned int*)&p3;
    return o;
}

// add-only aggregation core (h rows are pre-scaled hw = dinv*h)
__device__ __forceinline__ void agg_sum(const uint4* __restrict__ h4, int n,
                                        int lane, float* acc) {
    float f0[8], f1[8], f2[8], f3[8];
    unp8(h4[(size_t)n * 16 + lane], acc);     // self term

    int i   = g_rowstart[n];
    int end = g_rowstart[n + 1];
    for (; i + 7 < end; i += 8) {
        int   si[8];
        uint4 vi[8];
#pragma unroll
        for (int j = 0; j < 8; j++) si[j] = g_csri[i + j];
#pragma unroll
        for (int j = 0; j < 8; j++) vi[j] = h4[(size_t)si[j] * 16 + lane];
#pragma unroll
        for (int j = 0; j < 8; j++) {
            unp8(vi[j], f0);
#pragma unroll
            for (int k = 0; k < 8; k++) acc[k] += f0[k];
        }
    }
    for (; i + 3 < end; i += 4) {
        int s0 = g_csri[i],     s1 = g_csri[i + 1];
        int s2 = g_csri[i + 2], s3 = g_csri[i + 3];
        uint4 v0 = h4[(size_t)s0 * 16 + lane];
        uint4 v1 = h4[(size_t)s1 * 16 + lane];
        uint4 v2 = h4[(size_t)s2 * 16 + lane];
        uint4 v3 = h4[(size_t)s3 * 16 + lane];
        unp8(v0, f0); unp8(v1, f1); unp8(v2, f2); unp8(v3, f3);
#pragma unroll
        for (int k = 0; k < 8; k++)
            acc[k] += f0[k] + f1[k] + f2[k] + f3[k];
    }
    for (; i < end; i++) {
        int s0 = g_csri[i];
        uint4 v0 = h4[(size_t)s0 * 16 + lane];
        unp8(v0, f0);
#pragma unroll
        for (int k = 0; k < 8; k++) acc[k] += f0[k];
    }
}

// ---------------- gather, weighted (layer 1: h not pre-scaled) --------------
// writes dinv[n] * relu( dinv[n] * (sum_s dinv[s]h[s] + dinv[n]h[n]) )
__global__ void __launch_bounds__(256) k_gather_w(const __half* __restrict__ h,
                                                  __half* __restrict__ out) {
    int hw   = (blockIdx.x * blockDim.x + threadIdx.x) >> 4;
    int lane = threadIdx.x & 15;
    if (hw >= NN) return;
    int n = hw;

    const uint4* h4 = (const uint4*)h;
    float di = g_dinv[n];
    float acc[8], f0[8], f1[8], f2[8], f3[8];
    unp8(h4[(size_t)n * 16 + lane], acc);
#pragma unroll
    for (int k = 0; k < 8; k++) acc[k] *= di;

    int i   = g_rowstart[n];
    int end = g_rowstart[n + 1];
    for (; i + 3 < end; i += 4) {
        int s0 = g_csri[i],     s1 = g_csri[i + 1];
        int s2 = g_csri[i + 2], s3 = g_csri[i + 3];
        float w0 = __ldg(&g_dinv[s0]), w1 = __ldg(&g_dinv[s1]);
        float w2 = __ldg(&g_dinv[s2]), w3 = __ldg(&g_dinv[s3]);
        uint4 v0 = h4[(size_t)s0 * 16 + lane];
        uint4 v1 = h4[(size_t)s1 * 16 + lane];
        uint4 v2 = h4[(size_t)s2 * 16 + lane];
        uint4 v3 = h4[(size_t)s3 * 16 + lane];
        unp8(v0, f0); unp8(v1, f1); unp8(v2, f2); unp8(v3, f3);
#pragma unroll
        for (int k = 0; k < 8; k++)
            acc[k] += w0 * f0[k] + w1 * f1[k] + w2 * f2[k] + w3 * f3[k];
    }
    for (; i < end; i++) {
        int s0 = g_csri[i];
        float w0 = __ldg(&g_dinv[s0]);
        uint4 v0 = h4[(size_t)s0 * 16 + lane];
        unp8(v0, f0);
#pragma unroll
        for (int k = 0; k < 8; k++) acc[k] += w0 * f0[k];
    }
#pragma unroll
    for (int k = 0; k < 8; k++) {
        acc[k] *= di;
        acc[k] = fmaxf(acc[k], 0.0f);
        acc[k] *= di;                     // pre-scale for next gemm
    }
    ((uint4*)out)[(size_t)n * 16 + lane] = pack8(acc);
}

// ---------------- gather, add-only (layer 2: writes pre-scaled act) ---------
__global__ void __launch_bounds__(256) k_gather_f(const __half* __restrict__ h,
                                                  __half* __restrict__ out) {
    int hw   = (blockIdx.x * blockDim.x + threadIdx.x) >> 4;
    int lane = threadIdx.x & 15;
    if (hw >= NN) return;
    int n = hw;

    const uint4* h4 = (const uint4*)h;
    float acc[8];
    agg_sum(h4, n, lane, acc);

    float di = g_dinv[n];
#pragma unroll
    for (int k = 0; k < 8; k++) {
        acc[k] *= di;
        acc[k] = fmaxf(acc[k], 0.0f);
        acc[k] *= di;
    }
    ((uint4*)out)[(size_t)n * 16 + lane] = pack8(acc);
}

// ---------------- final gather + pool fused ---------------------------------
// Computes h3[n] = dinv[n]*sum and accumulates per-graph sums via smem staging.
__global__ void __launch_bounds__(256) k_gather_pool(const __half* __restrict__ h) {
    __shared__ float sacc[16 * HH];       // 8 KB: 16 nodes x 128 feats
    int hw   = threadIdx.x >> 4;          // 0..15 : node within block
    int lane = threadIdx.x & 15;
    int nbase = blockIdx.x * 16;
    int n = nbase + hw;

    float acc[8] = {0.f, 0.f, 0.f, 0.f, 0.f, 0.f, 0.f, 0.f};
    if (n < NN) {
        const uint4* h4 = (const uint4*)h;
        agg_sum(h4, n, lane, acc);
        float di = g_dinv[n];
#pragma unroll
        for (int k = 0; k < 8; k++) acc[k] *= di;
    }
    // stage to smem (two float4 stores)
    float4* s4 = (float4*)&sacc[hw * HH + lane * 8];
    s4[0] = make_float4(acc[0], acc[1], acc[2], acc[3]);
    s4[1] = make_float4(acc[4], acc[5], acc[6], acc[7]);
    __syncthreads();

    // 128 threads reduce over the block's 16 (sorted-batch) nodes
    int t = threadIdx.x;
    if (t < HH) {
        int nEnd = min(nbase + 16, NN);
        if (nbase < NN) {
            float run = 0.0f;
            int g = g_batch[nbase];
            for (int j = nbase; j < nEnd; j++) {
                int b = g_batch[j];
                if (b != g) {
                    atomicAdd(&g_pooled[g * HH + t], run);
                    run = 0.0f;
                    g = b;
                }
                run += sacc[(j - nbase) * HH + t];
            }
            atomicAdd(&g_pooled[g * HH + t], run);
        }
    }
}

// ---------------- final MLP: one block per graph -----------------------------
__global__ void __launch_bounds__(128) k_mlp(const float* __restrict__ M0w,
                                             const float* __restrict__ M0b,
                                             const float* __restrict__ M1w,
                                             const float* __restrict__ M1b,
                                             float* __restrict__ out) {
    __shared__ float pv[HH];
    __shared__ float hid[HH];
    int g = blockIdx.x;
    int t = threadIdx.x;
    pv[t] = g_pooled[g * HH + t] / fmaxf(g_cnts[g], 1.0f);
    __syncthreads();
    float s = M0b[t];
#pragma unroll 8
    for (int k = 0; k < HH; k++) s += pv[k] * M0w[k * HH + t];
    hid[t] = fmaxf(s, 0.0f);
    __syncthreads();
    if (t < OUTD) {
        float s2 = M1b[t];
#pragma unroll 8
        for (int j = 0; j < HH; j++) s2 += hid[j] * M1w[j * OUTD + t];
        out[g * OUTD + t] = s2;
    }
}

// ---------------- launch ----------------------------------------------------
extern "C" void kernel_launch(void* const* d_in, const int* in_sizes, int n_in,
                              void* d_out, int out_size) {
    const float* x   = (const float*)d_in[0];
    const float* W0  = (const float*)d_in[1];
    const float* W1  = (const float*)d_in[2];
    const float* W2  = (const float*)d_in[3];
    const float* M0w = (const float*)d_in[4];
    const float* M0b = (const float*)d_in[5];
    const float* M1w = (const float*)d_in[6];
    const float* M1b = (const float*)d_in[7];
    const void*  ei  = d_in[8];
    const void*  bat = d_in[9];
    float* out = (float*)d_out;

    __half* hA = nullptr;
    __half* hB = nullptr;
    __half* w16 = nullptr;
    cudaGetSymbolAddress((void**)&hA, g_h16a);
    cudaGetSymbolAddress((void**)&hB, g_h16b);
    cudaGetSymbolAddress((void**)&w16, g_w16);

    static int init_done = 0;
    static cudaStream_t s2 = nullptr;
    static cudaEvent_t ev0 = nullptr, ev1 = nullptr;
    static int streams_ok = 0;
    if (!init_done) {
        cudaFuncSetAttribute(k_gemm, cudaFuncAttributeMaxDynamicSharedMemorySize, SMEM_GEMM);
        cudaFuncSetAttribute(k_gemm_f32in, cudaFuncAttributeMaxDynamicSharedMemorySize, SMEM_GEMM);
        if (cudaStreamCreateWithFlags(&s2, cudaStreamNonBlocking) == cudaSuccess &&
            cudaEventCreateWithFlags(&ev0, cudaEventDisableTiming) == cudaSuccess &&
            cudaEventCreateWithFlags(&ev1, cudaEventDisableTiming) == cudaSuccess)
            streams_ok = 1;
        init_done = 1;
    }

    const int T = 256;
    int gN = (NN + T - 1) / T;              // 196
    int gE = (EE + T - 1) / T;              // 3125
    int gGemm   = (NN + 127) / 128;         // 391
    int gGather = (NN * 16 + T - 1) / T;    // 3125
    int gW      = (3 * HH * HH / 4 + T - 1) / T;   // 48

    cudaStream_t sb = streams_ok ? s2 : (cudaStream_t)0;

    // init, then fork chains A (CSR) / B (weights + gemm1 + batch)
    k_init<<<NBLK + 1, 256>>>((const int*)ei);
    if (streams_ok) {
        cudaEventRecord(ev0, 0);
        cudaStreamWaitEvent(s2, ev0, 0);
    }
    k_hist<<<gE, T>>>(ei);
    k_scan1<<<NBLK, 256>>>();
    k_scan3<<<NBLK, 256>>>();
    k_fill<<<gE, T>>>(ei);
    k_cvtw<<<gW, T, 0, sb>>>(W0, W1, W2);
    k_gemm_f32in<<<gGemm, T, SMEM_GEMM, sb>>>(x, w16, hB, NN);
    k_cvt_batch<<<gN, T, 0, sb>>>(bat);
    if (streams_ok) {
        cudaEventRecord(ev1, s2);
        cudaStreamWaitEvent(0, ev1, 0);
    }

    // layer 1: weighted gather, writes pre-scaled act
    k_gather_w<<<gGather, T>>>(hB, hA);
    // layer 2: gemm -> hw2; add-only gather, writes pre-scaled act
    k_gemm<<<gGemm, T, SMEM_GEMM>>>(hA, w16 + HH * HH, hB, NN);
    k_gather_f<<<gGather, T>>>(hB, hA);
    // layer 3: gemm -> hw3; fused gather+pool (no h3 materialization)
    k_gemm<<<gGemm, T, SMEM_GEMM>>>(hA, w16 + 2 * HH * HH, hB, NN);
    k_gather_pool<<<gGather, T>>>(hB);

    k_mlp<<<GG, 128>>>(M0w, M0b, M1w, M1b, out);
}